// round 9
// baseline (speedup 1.0000x reference)
#include <cuda_runtime.h>
#include <math_constants.h>

#define BB 2
#define HH 256
#define WW 256
#define PTS 64
#define IMP 64
#define NRAYS (BB*HH*WW)          // 131072
#define NEARP 0.1f
#define FARP  2.0f
#define DSTEP ((FARP-NEARP)/63.0f)
#define FOCAL 4.2f

#define OFS_C 0
#define OFS_F (BB*3*HH*WW)        // 393216
#define OFS_D (2*BB*3*HH*WW)      // 786432

#define NBLOCKS (NRAYS / 128)     // 1024
#define EPS_ABS 1e-8f             // transmittance cutoff; residual contributions < 64*1e-8

// statically initialized; reset by the LAST block each run (graph-replay safe)
__device__ int g_min_bits = 0x7f800000;
__device__ int g_max_bits = 0;
__device__ int g_arrive   = 0;
__device__ int g_release  = 0;
__device__ int g_done     = 0;

__device__ __forceinline__ float tanh_approx(float x) {
    float y;
    asm("tanh.approx.f32 %0, %1;" : "=f"(y) : "f"(x));
    return y;
}

// caller pre-halves the argument: sigmoid(2x') = 0.5*tanh(x') + 0.5
__device__ __forceinline__ float sigm_h(float xh) {
    return fmaf(tanh_approx(xh), 0.5f, 0.5f);
}

// __launch_bounds__(128, 7): 7 blocks/SM * 148 SMs = 1036 >= 1024 blocks
// -> entire grid co-resident in wave 1 -> grid-wide spin barrier is safe.
__global__ void __launch_bounds__(128, 7) render_kernel(
    const float* __restrict__ tm,   // (B,3,4)
    const float* __restrict__ Wq,   // (6,4)
    float* __restrict__ out)
{
    __shared__ float s_mn, s_mx;

    int r = blockIdx.x * blockDim.x + threadIdx.x;   // grid covers rays exactly; all lanes active
    int b = r >> 16;
    int n = r & 65535;
    int iy = n >> 8;       // image row
    int jx = n & 255;      // image col

    float cx = fmaf((float)jx, -2.0f / 255.0f, 1.0f) * (1.0f / FOCAL);
    float cy = fmaf((float)iy, -2.0f / 255.0f, 1.0f) * (1.0f / FOCAL);

    const float* T = tm + b * 12;
    float dx = __ldg(T + 0) * cx + __ldg(T + 1) * cy + __ldg(T + 2);
    float dy = __ldg(T + 4) * cx + __ldg(T + 5) * cy + __ldg(T + 6);
    float dz = __ldg(T + 8) * cx + __ldg(T + 9) * cy + __ldg(T + 10);
    float ox = __ldg(T + 3), oy = __ldg(T + 7), oz = __ldg(T + 11);

    // 0.5 * feat(depth)[c] = base[c] + depth * kk[c]   (0.5 folded in for tanh)
    float base[4], kk[4];
#pragma unroll
    for (int c = 0; c < 4; c++) {
        base[c] = 0.5f * (ox * __ldg(Wq + 0 * 4 + c) + oy * __ldg(Wq + 1 * 4 + c) + oz * __ldg(Wq + 2 * 4 + c)
                        + dx * __ldg(Wq + 3 * 4 + c) + dy * __ldg(Wq + 4 * 4 + c) + dz * __ldg(Wq + 5 * 4 + c));
        kk[c]   = 0.5f * (dx * __ldg(Wq + 0 * 4 + c) + dy * __ldg(Wq + 1 * 4 + c) + dz * __ldg(Wq + 2 * 4 + c));
    }

    float cdf[PTS];   // unnormalized cumsum of (w + 1e-5)

    // ---------------- Pass 1: coarse ray march + cdf build (early-exit) ----------------
    float absorption = 1.0f;
    float a0 = 0.0f, a1 = 0.0f, a2 = 0.0f;
    float cum = 0.0f;
    {
        int p = 0;
#pragma unroll 1
        for (; p < PTS; p++) {
            float d = NEARP + p * DSTEP;
            float op = sigm_h(fmaf(d, kk[0], base[0]));
            float v0 = sigm_h(fmaf(d, kk[1], base[1]));
            float v1 = sigm_h(fmaf(d, kk[2], base[2]));
            float v2 = sigm_h(fmaf(d, kk[3], base[3]));
            float w = op * absorption;
            absorption *= (1.0f - op);
            a0 = fmaf(w, v0, a0);
            a1 = fmaf(w, v1, a1);
            a2 = fmaf(w, v2, a2);
            cum += w + 1e-5f;
            cdf[p] = cum;
            if (__all_sync(0xffffffffu, absorption < EPS_ABS)) { p++; break; }
        }
        // tanh-free tail: w <= absorption < EPS -> increment is (w + 1e-5) ~= 1e-5
#pragma unroll 1
        for (; p < PTS; p++) {
            cum += 1e-5f;
            cdf[p] = cum;
        }
    }
    out[OFS_C + ((b * 3 + 0) << 16) + n] = a0;
    out[OFS_C + ((b * 3 + 1) << 16) + n] = a1;
    out[OFS_C + ((b * 3 + 2) << 16) + n] = a2;

    float inv_total = __fdividef(1.0f, cum);

    // ---------------- Fused pass 2+3: streaming CDF inversion inside the merge ----------------
    int   jp    = 0;
    float c_jm1 = 0.0f,  d_jm1 = NEARP;            // cdf_n[jp-1], depth[jp-1] (valid once jp>=1)
    float c_j   = cdf[0] * inv_total, d_j = NEARP; // cdf_n[jp],   depth[jp]
    float u     = 0.0f;                            // k/64, exact under incremental FADD

    auto gen_bin = [&]() -> float {
        while (jp < PTS && c_j <= u) {
            jp++;
            c_jm1 = c_j;  d_jm1 = d_j;
            if (jp < PTS) { c_j = cdf[jp] * inv_total; d_j += DSTEP; }
            else          { c_j = CUDART_INF_F; }
        }
        float c0 = (jp == 0)   ? c_j   : c_jm1;
        float d0 = (jp == 0)   ? d_j   : d_jm1;
        float c1 = (jp < PTS)  ? c_j   : c_jm1;
        float d1 = (jp < PTS)  ? d_j   : d_jm1;
        float dd = c1 - c0;
        float denom = (dd < 1e-8f) ? 1.0f : dd;
        float t = __fdividef(u - c0, denom);
        t = fminf(fmaxf(t, 0.0f), 1.0f);
        return fmaf(t, d1 - d0, d0);
    };

    float prev_bin = gen_bin();  u += (1.0f / 64.0f);   // bin_0 (== NEARP)
    float bin      = gen_bin();  u += (1.0f / 64.0f);   // bin_1
    float df = 0.5f * (prev_bin + bin);
    prev_bin = bin;
    int kf = 2;        // next bin index to generate
    int ic = 0;        // coarse points consumed
    float dc = NEARP;  // next coarse depth (incremental)

    absorption = 1.0f;
    a0 = a1 = a2 = 0.0f;
    float wsum = 0.0f, dsum = 0.0f;
#pragma unroll 1
    for (int m = 0; m < PTS + IMP; m++) {
        // remaining weights bounded by absorption -> residuals < 128*EPS, far below tolerance
        if (__all_sync(0xffffffffu, absorption < EPS_ABS)) break;
        bool take_c = (ic < PTS) && (dc <= df);    // df==+inf once fine exhausted
        float d = take_c ? dc : df;
        float op = sigm_h(fmaf(d, kk[0], base[0]));
        float v0 = sigm_h(fmaf(d, kk[1], base[1]));
        float v1 = sigm_h(fmaf(d, kk[2], base[2]));
        float v2 = sigm_h(fmaf(d, kk[3], base[3]));
        float w = op * absorption;
        absorption *= (1.0f - op);
        a0 = fmaf(w, v0, a0);
        a1 = fmaf(w, v1, a1);
        a2 = fmaf(w, v2, a2);
        wsum += w;
        dsum = fmaf(w, d, dsum);
        if (take_c) {
            ic++; dc += DSTEP;
        } else {
            if (kf <= IMP) {
                bin = gen_bin();  u += (1.0f / 64.0f);
                df = 0.5f * (prev_bin + bin);
                prev_bin = bin;
                kf++;
            } else {
                df = CUDART_INF_F;
            }
        }
    }
    out[OFS_F + ((b * 3 + 0) << 16) + n] = a0;
    out[OFS_F + ((b * 3 + 1) << 16) + n] = a1;
    out[OFS_F + ((b * 3 + 2) << 16) + n] = a2;

    // ray depth: sum(w*d) + (1 - clip(sum w,0,1)) * max(d_all) [= FAR exactly]
    float f_accum_op = fminf(wsum, 1.0f);
    float rd = dsum + (1.0f - f_accum_op) * FARP;

    // ---------------- global min/max + grid-wide barrier + normalize ----------------
    float mn = rd, mx = rd;
#pragma unroll
    for (int o = 16; o > 0; o >>= 1) {
        mn = fminf(mn, __shfl_xor_sync(0xffffffffu, mn, o));
        mx = fmaxf(mx, __shfl_xor_sync(0xffffffffu, mx, o));
    }
    if ((threadIdx.x & 31) == 0) {
        atomicMin(&g_min_bits, __float_as_int(mn));   // rd > 0: int order == float order
        atomicMax(&g_max_bits, __float_as_int(mx));
    }
    __syncthreads();

    // grid-wide barrier: whole grid is resident (launch_bounds guarantees it)
    if (threadIdx.x == 0) {
        __threadfence();
        int t = atomicAdd(&g_arrive, 1);
        if (t == NBLOCKS - 1) {
            g_arrive = 0;
            __threadfence();
            atomicExch(&g_release, 1);
        } else {
            while (atomicAdd(&g_release, 0) == 0) { __nanosleep(64); }
        }
        s_mn = __int_as_float(__ldcg(&g_min_bits));
        s_mx = __int_as_float(__ldcg(&g_max_bits));
    }
    __syncthreads();

    float inv = __fdividef(1.0f, s_mx - s_mn);
    out[OFS_D + (b << 16) + n] = (rd - s_mn) * inv;

    // reset state for the next graph replay (after every block has read min/max)
    __syncthreads();
    if (threadIdx.x == 0) {
        int t = atomicAdd(&g_done, 1);
        if (t == NBLOCKS - 1) {
            g_done     = 0;
            g_release  = 0;
            g_min_bits = 0x7f800000;
            g_max_bits = 0;
            __threadfence();
        }
    }
}

extern "C" void kernel_launch(void* const* d_in, const int* in_sizes, int n_in,
                              void* d_out, int out_size) {
    const float* tm = (const float*)d_in[0];   // transform_matrix (2,3,4)
    const float* Wq = (const float*)d_in[1];   // W_query (6,4)
    float* out = (float*)d_out;

    render_kernel<<<NBLOCKS, 128>>>(tm, Wq, out);
}

// round 12
// speedup vs baseline: 1.0938x; 1.0938x over previous
#include <cuda_runtime.h>
#include <math_constants.h>

#define BB 2
#define HH 256
#define WW 256
#define PTS 64
#define IMP 64
#define NRAYS (BB*HH*WW)          // 131072
#define NEARP 0.1f
#define FARP  2.0f
#define DSTEP ((FARP-NEARP)/63.0f)
#define FOCAL 4.2f

#define OFS_C 0
#define OFS_F (BB*3*HH*WW)        // 393216
#define OFS_D (2*BB*3*HH*WW)      // 786432

#define NBLOCKS (NRAYS / 128)     // 1024
#define EPS_ABS 1e-8f             // transmittance cutoff; residual contributions ~1e-6

// statically initialized; reset by the LAST block each run (graph-replay safe)
__device__ int g_min_bits = 0x7f800000;
__device__ int g_max_bits = 0;
__device__ int g_arrive   = 0;
__device__ int g_release  = 0;
__device__ int g_done     = 0;

__device__ __forceinline__ float tanh_approx(float x) {
    float y;
    asm("tanh.approx.f32 %0, %1;" : "=f"(y) : "f"(x));
    return y;
}

// caller pre-halves the argument: sigmoid(2x') = 0.5*tanh(x') + 0.5
__device__ __forceinline__ float sigm_h(float xh) {
    return fmaf(tanh_approx(xh), 0.5f, 0.5f);
}

// __launch_bounds__(128, 7): 7 blocks/SM * 148 SMs = 1036 >= 1024 blocks
// -> entire grid co-resident in wave 1 -> grid-wide spin barrier is safe.
__global__ void __launch_bounds__(128, 7) render_kernel(
    const float* __restrict__ tm,   // (B,3,4)
    const float* __restrict__ Wq,   // (6,4)
    float* __restrict__ out)
{
    __shared__ float s_mn, s_mx;

    int r = blockIdx.x * blockDim.x + threadIdx.x;   // grid covers rays exactly; all lanes active
    int b = r >> 16;
    int n = r & 65535;
    int iy = n >> 8;       // image row
    int jx = n & 255;      // image col

    float cx = fmaf((float)jx, -2.0f / 255.0f, 1.0f) * (1.0f / FOCAL);
    float cy = fmaf((float)iy, -2.0f / 255.0f, 1.0f) * (1.0f / FOCAL);

    const float* T = tm + b * 12;
    float dx = __ldg(T + 0) * cx + __ldg(T + 1) * cy + __ldg(T + 2);
    float dy = __ldg(T + 4) * cx + __ldg(T + 5) * cy + __ldg(T + 6);
    float dz = __ldg(T + 8) * cx + __ldg(T + 9) * cy + __ldg(T + 10);
    float ox = __ldg(T + 3), oy = __ldg(T + 7), oz = __ldg(T + 11);

    // 0.5 * feat(depth)[c] = base[c] + depth * kk[c]   (0.5 folded in for tanh)
    float base[4], kk[4];
#pragma unroll
    for (int c = 0; c < 4; c++) {
        base[c] = 0.5f * (ox * __ldg(Wq + 0 * 4 + c) + oy * __ldg(Wq + 1 * 4 + c) + oz * __ldg(Wq + 2 * 4 + c)
                        + dx * __ldg(Wq + 3 * 4 + c) + dy * __ldg(Wq + 4 * 4 + c) + dz * __ldg(Wq + 5 * 4 + c));
        kk[c]   = 0.5f * (dx * __ldg(Wq + 0 * 4 + c) + dy * __ldg(Wq + 1 * 4 + c) + dz * __ldg(Wq + 2 * 4 + c));
    }

    float cdf[PTS];   // unnormalized cumsum of (w + 1e-5)

    // ---------------- Pass 1: coarse ray march + cdf build ----------------
    // Chunked by 8: 32 independent tanh per chunk front-batched; exit check per chunk.
    float absorption = 1.0f;
    float a0 = 0.0f, a1 = 0.0f, a2 = 0.0f;
    float cum = 0.0f;
    {
        int p = PTS;
#pragma unroll 1
        for (int ch = 0; ch < PTS / 8; ch++) {
            int pbase = ch * 8;
#pragma unroll
            for (int i = 0; i < 8; i++) {
                float d = NEARP + (pbase + i) * DSTEP;
                float op = sigm_h(fmaf(d, kk[0], base[0]));
                float v0 = sigm_h(fmaf(d, kk[1], base[1]));
                float v1 = sigm_h(fmaf(d, kk[2], base[2]));
                float v2 = sigm_h(fmaf(d, kk[3], base[3]));
                float w = op * absorption;
                absorption *= (1.0f - op);
                a0 = fmaf(w, v0, a0);
                a1 = fmaf(w, v1, a1);
                a2 = fmaf(w, v2, a2);
                cum += w + 1e-5f;
                cdf[pbase + i] = cum;
            }
            if (__all_sync(0xffffffffu, absorption < EPS_ABS)) { p = pbase + 8; break; }
        }
        // tanh-free tail: w <= absorption < EPS -> increment is ~1e-5
#pragma unroll 1
        for (; p < PTS; p++) {
            cum += 1e-5f;
            cdf[p] = cum;
        }
    }
    out[OFS_C + ((b * 3 + 0) << 16) + n] = a0;
    out[OFS_C + ((b * 3 + 1) << 16) + n] = a1;
    out[OFS_C + ((b * 3 + 2) << 16) + n] = a2;

    float inv_total = __fdividef(1.0f, cum);

    // ---------------- Fused pass 2+3, chunked: generate 4 depths, then evaluate 16 tanh ----------------
    int   jp    = 0;
    float c_jm1 = 0.0f,  d_jm1 = NEARP;            // cdf_n[jp-1], depth[jp-1] (valid once jp>=1)
    float c_j   = cdf[0] * inv_total, d_j = NEARP; // cdf_n[jp],   depth[jp]
    float u     = 0.0f;                            // k/64, exact under incremental FADD

    auto gen_bin = [&]() -> float {
        while (jp < PTS && c_j <= u) {
            jp++;
            c_jm1 = c_j;  d_jm1 = d_j;
            if (jp < PTS) { c_j = cdf[jp] * inv_total; d_j += DSTEP; }
            else          { c_j = CUDART_INF_F; }
        }
        float c0 = (jp == 0)   ? c_j   : c_jm1;
        float d0 = (jp == 0)   ? d_j   : d_jm1;
        float c1 = (jp < PTS)  ? c_j   : c_jm1;
        float d1 = (jp < PTS)  ? d_j   : d_jm1;
        float dd = c1 - c0;
        float denom = (dd < 1e-8f) ? 1.0f : dd;
        float t = __fdividef(u - c0, denom);
        t = fminf(fmaxf(t, 0.0f), 1.0f);
        return fmaf(t, d1 - d0, d0);
    };

    float prev_bin = gen_bin();  u += (1.0f / 64.0f);   // bin_0 (== NEARP)
    float bin      = gen_bin();  u += (1.0f / 64.0f);   // bin_1
    float df = 0.5f * (prev_bin + bin);
    prev_bin = bin;
    int kf = 2;        // next bin index to generate
    int ic = 0;        // coarse points consumed
    float dc = NEARP;  // next coarse depth (incremental)

    absorption = 1.0f;
    a0 = a1 = a2 = 0.0f;
    float wsum = 0.0f, dsum = 0.0f;
#pragma unroll 1
    for (int ch = 0; ch < (PTS + IMP) / 4; ch++) {
        // --- generation burst: depth sequence depends only on cdf, never on tanh results ---
        float db[4];
#pragma unroll
        for (int i = 0; i < 4; i++) {
            bool take_c = (ic < PTS) && (dc <= df);    // df==+inf once fine exhausted
            db[i] = take_c ? dc : df;
            if (take_c) {
                ic++; dc += DSTEP;
            } else {
                if (kf <= IMP) {
                    bin = gen_bin();  u += (1.0f / 64.0f);
                    df = 0.5f * (prev_bin + bin);
                    prev_bin = bin;
                    kf++;
                } else {
                    df = CUDART_INF_F;
                }
            }
        }
        // --- evaluation burst: 16 independent tanh, short FMA accumulation chains ---
#pragma unroll
        for (int i = 0; i < 4; i++) {
            float d = db[i];
            float op = sigm_h(fmaf(d, kk[0], base[0]));
            float v0 = sigm_h(fmaf(d, kk[1], base[1]));
            float v1 = sigm_h(fmaf(d, kk[2], base[2]));
            float v2 = sigm_h(fmaf(d, kk[3], base[3]));
            float w = op * absorption;
            absorption *= (1.0f - op);
            a0 = fmaf(w, v0, a0);
            a1 = fmaf(w, v1, a1);
            a2 = fmaf(w, v2, a2);
            wsum += w;
            dsum = fmaf(w, d, dsum);
        }
        if (__all_sync(0xffffffffu, absorption < EPS_ABS)) break;
    }
    out[OFS_F + ((b * 3 + 0) << 16) + n] = a0;
    out[OFS_F + ((b * 3 + 1) << 16) + n] = a1;
    out[OFS_F + ((b * 3 + 2) << 16) + n] = a2;

    // ray depth: sum(w*d) + (1 - clip(sum w,0,1)) * max(d_all) [= FAR exactly]
    float f_accum_op = fminf(wsum, 1.0f);
    float rd = dsum + (1.0f - f_accum_op) * FARP;

    // ---------------- global min/max + grid-wide barrier + normalize ----------------
    float mn = rd, mx = rd;
#pragma unroll
    for (int o = 16; o > 0; o >>= 1) {
        mn = fminf(mn, __shfl_xor_sync(0xffffffffu, mn, o));
        mx = fmaxf(mx, __shfl_xor_sync(0xffffffffu, mx, o));
    }
    if ((threadIdx.x & 31) == 0) {
        atomicMin(&g_min_bits, __float_as_int(mn));   // rd > 0: int order == float order
        atomicMax(&g_max_bits, __float_as_int(mx));
    }
    __syncthreads();

    // grid-wide barrier: whole grid is resident (launch_bounds guarantees it)
    if (threadIdx.x == 0) {
        __threadfence();
        int t = atomicAdd(&g_arrive, 1);
        if (t == NBLOCKS - 1) {
            g_arrive = 0;
            __threadfence();
            atomicExch(&g_release, 1);
        } else {
            while (atomicAdd(&g_release, 0) == 0) { __nanosleep(64); }
        }
        s_mn = __int_as_float(__ldcg(&g_min_bits));
        s_mx = __int_as_float(__ldcg(&g_max_bits));
    }
    __syncthreads();

    float inv = __fdividef(1.0f, s_mx - s_mn);
    out[OFS_D + (b << 16) + n] = (rd - s_mn) * inv;

    // reset state for the next graph replay (after every block has read min/max)
    __syncthreads();
    if (threadIdx.x == 0) {
        int t = atomicAdd(&g_done, 1);
        if (t == NBLOCKS - 1) {
            g_done     = 0;
            g_release  = 0;
            g_min_bits = 0x7f800000;
            g_max_bits = 0;
            __threadfence();
        }
    }
}

extern "C" void kernel_launch(void* const* d_in, const int* in_sizes, int n_in,
                              void* d_out, int out_size) {
    const float* tm = (const float*)d_in[0];   // transform_matrix (2,3,4)
    const float* Wq = (const float*)d_in[1];   // W_query (6,4)
    float* out = (float*)d_out;

    render_kernel<<<NBLOCKS, 128>>>(tm, Wq, out);
}